// round 5
// baseline (speedup 1.0000x reference)
#include <cuda_runtime.h>
#include <cuda_bf16.h>

#define NN 20000
#define DD 32
#define HH 64
#define GG 256     // 4*H
#define MT 48      // nodes per LSTM block
#define HSTR 50    // padded node stride (even for LDS.64, gcd(50,32)=2)

typedef unsigned long long u64;

// ---------------- device scratch (no allocations allowed) ----------------
__device__ int   g_nbrs[NN * DD];
__device__ float g_bufA[NN * HH];
__device__ float g_bufB[NN * HH];
__device__ float g_proj[NN * GG];
__device__ float g_agg [NN * HH];

__device__ __forceinline__ float sigm(float x) {
    return __fdividef(1.f, 1.f + __expf(-x));
}
__device__ __forceinline__ float tanh_fast(float x) {
    x = fmaxf(-15.f, fminf(15.f, x));
    float e = __expf(-2.f * x);
    return __fdividef(1.f - e, 1.f + e);
}

// packed fp32x2 helpers (Blackwell FFMA2 path, PTX-only)
__device__ __forceinline__ u64 pack2(float lo, float hi) {
    u64 r;
    asm("mov.b64 %0, {%1, %2};" : "=l"(r) : "r"(__float_as_uint(lo)), "r"(__float_as_uint(hi)));
    return r;
}
__device__ __forceinline__ void unpack2(u64 v, float& lo, float& hi) {
    unsigned a, b;
    asm("mov.b64 {%0, %1}, %2;" : "=r"(a), "=r"(b) : "l"(v));
    lo = __uint_as_float(a); hi = __uint_as_float(b);
}
__device__ __forceinline__ u64 fma2(u64 a, u64 b, u64 c) {
    u64 d;
    asm("fma.rn.f32x2 %0, %1, %2, %3;" : "=l"(d) : "l"(a), "l"(b), "l"(c));
    return d;
}

// ---------------- sort neighbor rows (bitonic, registers, per thread) -----
__global__ void sort_kernel(const int* __restrict__ nbr) {
    int node = blockIdx.x * blockDim.x + threadIdx.x;
    if (node >= NN) return;
    int v[DD];
#pragma unroll
    for (int i = 0; i < DD; i++) v[i] = nbr[node * DD + i];
#pragma unroll
    for (int k = 2; k <= DD; k <<= 1) {
#pragma unroll
        for (int j = k >> 1; j > 0; j >>= 1) {
#pragma unroll
            for (int i = 0; i < DD; i++) {
                int l = i ^ j;
                if (l > i) {
                    int a = v[i], b = v[l];
                    bool up = ((i & k) == 0);
                    if ((a > b) == up) { v[i] = b; v[l] = a; }
                }
            }
        }
    }
#pragma unroll
    for (int i = 0; i < DD; i++) g_nbrs[node * DD + i] = v[i];
}

// ---------------- proj = x @ W_ih^T + b_ih + b_hh   [N,256] ---------------
__global__ void proj_kernel(const float* __restrict__ x, int in_d,
                            const float* __restrict__ W_ih,
                            const float* __restrict__ b_ih,
                            const float* __restrict__ b_hh) {
    extern __shared__ float sm[];
    float* sW = sm;                 // [in_d][256] (transposed W_ih)
    float* sB = sW + in_d * GG;     // [256]
    float* sX = sB + GG;            // [8][in_d]
    int tid = threadIdx.x;
    for (int idx = tid; idx < in_d * GG; idx += 256) {
        int g = idx / in_d, k = idx - g * in_d;
        sW[k * GG + g] = W_ih[idx];
    }
    if (tid < GG) sB[tid] = b_ih[tid] + b_hh[tid];
    int node0 = blockIdx.x * 8;
    for (int idx = tid; idx < 8 * in_d; idx += 256) {
        int i = idx / in_d, k = idx - i * in_d;
        sX[idx] = x[(node0 + i) * in_d + k];
    }
    __syncthreads();
    int w = tid >> 5, tg = tid & 31;
    float acc[8];
#pragma unroll
    for (int j = 0; j < 8; j++) acc[j] = sB[tg + 32 * j];
    for (int k = 0; k < in_d; k++) {
        float xv = sX[w * in_d + k];
#pragma unroll
        for (int j = 0; j < 8; j++) acc[j] += xv * sW[k * GG + tg + 32 * j];
    }
    int node = node0 + w;
#pragma unroll
    for (int j = 0; j < 8; j++) g_proj[node * GG + tg + 32 * j] = acc[j];
}

// ---------------- LSTM recurrence over 32 sorted-neighbor steps -----------
// 192 threads (6 warps) x 48 nodes. Each warp owns 8 nodes; its h-state
// columns in smem are touched by no other warp -> warp-level sync only.
// Accumulators packed over node pairs -> fma.rn.f32x2 (2x fp32 throughput).
__global__ __launch_bounds__(192, 2)
void lstm_kernel(const float* __restrict__ W_hh) {
    extern __shared__ float sm[];
    float* sW = sm;               // [64][256]: sW[k][g] = W_hh[g][k]
    float* sH = sm + HH * GG;     // [2][64][HSTR]
    int tid = threadIdx.x;
    int tg = tid & 31, tn = tid >> 5;
    for (int idx = tid; idx < GG * HH; idx += 192) {
        int g = idx >> 6, k = idx & 63;
        sW[k * GG + g] = W_hh[idx];
    }
    for (int idx = tid; idx < 2 * HH * HSTR; idx += 192) sH[idx] = 0.f;
    __syncthreads();

    int node0 = blockIdx.x * MT + tn * 8;
    int base = tn * 8;
    float c0[8], c1[8], h0[8], h1[8];
#pragma unroll
    for (int i = 0; i < 8; i++) { c0[i] = 0.f; c1[i] = 0.f; h0[i] = 0.f; h1[i] = 0.f; }

    // lambda: apply LSTM cell for node i given its 8 gate values
    auto cell = [&](const float* g, int i) {
        float ig0 = sigm(g[0]), ig1 = sigm(g[1]);
        float fg0 = sigm(g[2]), fg1 = sigm(g[3]);
        float gg0 = tanh_fast(g[4]), gg1 = tanh_fast(g[5]);
        float og0 = sigm(g[6]), og1 = sigm(g[7]);
        c0[i] = fg0 * c0[i] + ig0 * gg0;
        c1[i] = fg1 * c1[i] + ig1 * gg1;
        h0[i] = og0 * tanh_fast(c0[i]);
        h1[i] = og1 * tanh_fast(c1[i]);
    };

    int p = 0;
#pragma unroll 1
    for (int t = 0; t < DD; t++) {
        u64 acc[8][4];   // [gate j][node-pair m], halves = nodes 2m, 2m+1
        // gather proj rows of t-th sorted neighbor (coalesced 128B per j)
#pragma unroll
        for (int m = 0; m < 4; m++) {
            int na = node0 + 2 * m;
            int nb = na + 1;
            int ia = (na < NN) ? g_nbrs[na * DD + t] : 0;
            int ib = (nb < NN) ? g_nbrs[nb * DD + t] : 0;
            const float* pa = g_proj + ia * GG + tg;
            const float* pb = g_proj + ib * GG + tg;
#pragma unroll
            for (int j = 0; j < 8; j++)
                acc[j][m] = pack2(__ldg(&pa[32 * j]), __ldg(&pb[32 * j]));
        }
        // packed register-tiled GEMM: acc += h(old) @ W_hh^T   (skip at t=0, h==0)
        if (t) {
            const float* sHr = sH + p * (HH * HSTR);
#pragma unroll 2
            for (int k = 0; k < HH; k++) {
                u64 bb[8];
#pragma unroll
                for (int j = 0; j < 8; j++) {
                    float b = sW[k * GG + tg + 32 * j];
                    bb[j] = pack2(b, b);
                }
#pragma unroll
                for (int m = 0; m < 4; m++) {
                    u64 a2 = *(const u64*)(sHr + k * HSTR + base + 2 * m);   // LDS.64 broadcast
#pragma unroll
                    for (int j = 0; j < 8; j++) acc[j][m] = fma2(a2, bb[j], acc[j][m]);
                }
            }
        }
        // cell update + store new h pairs (this warp's columns only)
        float* sHw = sH + (p ^ 1) * (HH * HSTR);
#pragma unroll
        for (int m = 0; m < 4; m++) {
            float ga[8], gb[8];
#pragma unroll
            for (int j = 0; j < 8; j++) unpack2(acc[j][m], ga[j], gb[j]);
            cell(ga, 2 * m);
            cell(gb, 2 * m + 1);
            *(float2*)(sHw + tg * HSTR + base + 2 * m)        = make_float2(h0[2 * m], h0[2 * m + 1]);
            *(float2*)(sHw + (tg + 32) * HSTR + base + 2 * m) = make_float2(h1[2 * m], h1[2 * m + 1]);
        }
        __syncwarp();
        p ^= 1;
    }
#pragma unroll
    for (int i = 0; i < 8; i++) {
        int node = node0 + i;
        if (node < NN) {
            g_agg[node * HH + tg]      = h0[i];
            g_agg[node * HH + tg + 32] = h1[i];
        }
    }
}

// ---------------- h_next = relu([x, agg] @ Wl^T + bl) ---------------------
// 256 threads = 8 warps = 8 nodes; lane owns adjacent output pair (2tg,2tg+1)
// -> LDS.64 weights + FFMA2 + STG.64 (halves LSU + FMA work vs round 1)
__global__ void combine_kernel(const float* __restrict__ x, int in_d,
                               const float* __restrict__ Wl,
                               const float* __restrict__ bl,
                               float* __restrict__ out) {
    extern __shared__ float sm[];
    int C = in_d + HH;
    float* sW = sm;            // [C][64] (transposed Wl)
    float* sB = sW + C * HH;   // [64]
    float* sX = sB + HH;       // [8][C]
    int tid = threadIdx.x;
    for (int idx = tid; idx < C * HH; idx += 256) {
        int o = idx / C, k = idx - o * C;
        sW[k * HH + o] = Wl[idx];
    }
    if (tid < HH) sB[tid] = bl[tid];
    int node0 = blockIdx.x * 8;
    for (int idx = tid; idx < 8 * C; idx += 256) {
        int i = idx / C, k = idx - i * C;
        sX[idx] = (k < in_d) ? x[(node0 + i) * in_d + k]
                             : g_agg[(node0 + i) * HH + (k - in_d)];
    }
    __syncthreads();
    int w = tid >> 5, tg = tid & 31;
    u64 acc = *(const u64*)(sB + 2 * tg);
    for (int k = 0; k < C; k++) {
        float xv = sX[w * C + k];
        u64 xx = pack2(xv, xv);
        u64 wp = *(const u64*)(sW + k * HH + 2 * tg);
        acc = fma2(xx, wp, acc);
    }
    float a0, a1;
    unpack2(acc, a0, a1);
    int node = node0 + w;
    *(float2*)(out + node * HH + 2 * tg) = make_float2(fmaxf(a0, 0.f), fmaxf(a1, 0.f));
}

// ---------------- out = h @ W_out^T + b_out -------------------------------
__global__ void out_kernel(const float* __restrict__ h,
                           const float* __restrict__ W_out,
                           const float* __restrict__ b_out,
                           float* __restrict__ out) {
    int tid = threadIdx.x;
    int node = blockIdx.x * 8 + (tid >> 5);
    int tg = tid & 31;
    float a = h[node * HH + tg] * W_out[tg] + h[node * HH + tg + 32] * W_out[tg + 32];
#pragma unroll
    for (int s = 16; s > 0; s >>= 1) a += __shfl_down_sync(0xffffffffu, a, s);
    if (tg == 0) out[node] = a + b_out[0];
}

// ---------------- launcher ------------------------------------------------
extern "C" void kernel_launch(void* const* d_in, const int* in_sizes, int n_in,
                              void* d_out, int out_size) {
    const float* node_features = (const float*)d_in[0];
    const int*   nbr           = (const int*)d_in[1];
    const float *W_ih[3], *W_hh[3], *b_ih[3], *b_hh[3], *Wl[3], *bl[3];
    for (int l = 0; l < 3; l++) {
        W_ih[l] = (const float*)d_in[2 + 6 * l + 0];
        W_hh[l] = (const float*)d_in[2 + 6 * l + 1];
        b_ih[l] = (const float*)d_in[2 + 6 * l + 2];
        b_hh[l] = (const float*)d_in[2 + 6 * l + 3];
        Wl[l]   = (const float*)d_in[2 + 6 * l + 4];
        bl[l]   = (const float*)d_in[2 + 6 * l + 5];
    }
    const float* W_out = (const float*)d_in[20];
    const float* b_out = (const float*)d_in[21];
    float* out = (float*)d_out;

    float *bufA, *bufB;
    cudaGetSymbolAddress((void**)&bufA, g_bufA);
    cudaGetSymbolAddress((void**)&bufB, g_bufB);

    cudaFuncSetAttribute(proj_kernel, cudaFuncAttributeMaxDynamicSharedMemorySize, 70000);
    cudaFuncSetAttribute(lstm_kernel, cudaFuncAttributeMaxDynamicSharedMemorySize, 93000);

    sort_kernel<<<(NN + 255) / 256, 256>>>(nbr);

    const float* x = node_features;
    float* nxt = bufA;
    int grid_lstm = (NN + MT - 1) / MT;   // 417
    size_t lstm_sm = (size_t)(HH * GG + 2 * HH * HSTR) * 4;
    for (int l = 0; l < 3; l++) {
        int in_d = (l == 0) ? 3 : 64;
        size_t proj_sm = (size_t)(in_d * GG + GG + 8 * in_d) * 4;
        proj_kernel<<<NN / 8, 256, proj_sm>>>(x, in_d, W_ih[l], b_ih[l], b_hh[l]);
        lstm_kernel<<<grid_lstm, 192, lstm_sm>>>(W_hh[l]);
        int C = in_d + HH;
        size_t comb_sm = (size_t)(C * HH + HH + 8 * C) * 4;
        combine_kernel<<<NN / 8, 256, comb_sm>>>(x, in_d, Wl[l], bl[l], nxt);
        x = nxt;
        nxt = (nxt == bufA) ? bufB : bufA;
    }
    out_kernel<<<NN / 8, 256>>>(x, W_out, b_out, out);
}

// round 8
// speedup vs baseline: 1.1270x; 1.1270x over previous
#include <cuda_runtime.h>
#include <cuda_bf16.h>

#define NN 20000
#define DD 32
#define HH 64
#define GG 256
#define MT 48      // nodes per LSTM block
#define HSTR 50    // padded node stride (even for LDS.64, gcd(50,32)=2)

typedef unsigned long long u64;
typedef unsigned int u32;

// ---------------- device scratch (no allocations allowed) ----------------
__device__ int   g_nbrs[NN * DD];
__device__ float g_bufA[NN * HH];
__device__ float g_bufB[NN * HH];
__device__ float g_proj[NN * GG];
__device__ float g_agg [NN * HH];
__device__ float g_wT  [HH * GG];    // W_hh transposed: [k][g]

__device__ __forceinline__ float tanhx(float x) {
    float y; asm("tanh.approx.f32 %0, %1;" : "=f"(y) : "f"(x)); return y;
}
__device__ __forceinline__ float sigmx(float x) {
    return fmaf(tanhx(0.5f * x), 0.5f, 0.5f);
}
__device__ __forceinline__ u64 pack2(float lo, float hi) {
    u64 r;
    asm("mov.b64 %0, {%1, %2};" : "=l"(r) : "r"(__float_as_uint(lo)), "r"(__float_as_uint(hi)));
    return r;
}
__device__ __forceinline__ void unpack2(u64 v, float& lo, float& hi) {
    u32 a, b;
    asm("mov.b64 {%0, %1}, %2;" : "=r"(a), "=r"(b) : "l"(v));
    lo = __uint_as_float(a); hi = __uint_as_float(b);
}
__device__ __forceinline__ u64 fma2(u64 a, u64 b, u64 c) {
    u64 d;
    asm("fma.rn.f32x2 %0, %1, %2, %3;" : "=l"(d) : "l"(a), "l"(b), "l"(c));
    return d;
}

// ---------------- sort neighbor rows (bitonic, registers) ----------------
__global__ void sort_kernel(const int* __restrict__ nbr) {
    int node = blockIdx.x * blockDim.x + threadIdx.x;
    if (node >= NN) return;
    int v[DD];
#pragma unroll
    for (int i = 0; i < DD; i++) v[i] = nbr[node * DD + i];
#pragma unroll
    for (int k = 2; k <= DD; k <<= 1)
#pragma unroll
        for (int j = k >> 1; j > 0; j >>= 1)
#pragma unroll
            for (int i = 0; i < DD; i++) {
                int l = i ^ j;
                if (l > i) {
                    int a = v[i], b = v[l];
                    if ((a > b) == ((i & k) == 0)) { v[i] = b; v[l] = a; }
                }
            }
#pragma unroll
    for (int i = 0; i < DD; i++) g_nbrs[node * DD + i] = v[i];
}

// ---------------- transpose W_hh -> g_wT[k*256+g] -------------------------
__global__ void transw_kernel(const float* __restrict__ W) {
    int k = blockIdx.x, g = threadIdx.x;
    g_wT[k * GG + g] = W[g * HH + k];
}

// ---------------- proj = x @ W_ih^T + b_ih + b_hh  (32 nodes/block) -------
__global__ void proj_kernel(const float* __restrict__ x, int in_d,
                            const float* __restrict__ W_ih,
                            const float* __restrict__ b_ih,
                            const float* __restrict__ b_hh) {
    extern __shared__ float smf[];
    float* sW = smf;                 // [in_d][256] transposed
    float* sB = sW + in_d * GG;      // [256]
    float* sX = sB + GG;             // [32][in_d]
    int tid = threadIdx.x;
    for (int idx = tid; idx < in_d * GG; idx += 256) {
        int g = idx / in_d, k = idx - g * in_d;
        sW[k * GG + g] = W_ih[idx];
    }
    if (tid < GG) sB[tid] = b_ih[tid] + b_hh[tid];
    int node0 = blockIdx.x * 32;
    for (int idx = tid; idx < 32 * in_d; idx += 256) {
        int i = idx / in_d, k = idx - i * in_d;
        sX[idx] = x[(node0 + i) * in_d + k];
    }
    __syncthreads();
    int w = tid >> 5, tg = tid & 31;
    float acc[4][8];
#pragma unroll
    for (int i = 0; i < 4; i++)
#pragma unroll
        for (int j = 0; j < 8; j++) acc[i][j] = sB[tg + 32 * j];
    for (int k = 0; k < in_d; k++) {
        float xv[4];
#pragma unroll
        for (int i = 0; i < 4; i++) xv[i] = sX[(w * 4 + i) * in_d + k];
#pragma unroll
        for (int j = 0; j < 8; j++) {
            float b = sW[k * GG + tg + 32 * j];
#pragma unroll
            for (int i = 0; i < 4; i++) acc[i][j] += xv[i] * b;
        }
    }
#pragma unroll
    for (int i = 0; i < 4; i++) {
        int node = node0 + w * 4 + i;
#pragma unroll
        for (int j = 0; j < 8; j++) g_proj[node * GG + tg + 32 * j] = acc[i][j];
    }
}

// ---------------- LSTM recurrence (FFMA2, W from L1, occ 3) ---------------
// 192 threads (6 warps) x 48 nodes; warp owns 8 nodes, syncs only itself.
__global__ __launch_bounds__(192, 3)
void lstm_kernel() {
    __shared__ float sH[2 * HH * HSTR];   // 25.6 KB -> 3 CTAs/SM
    int tid = threadIdx.x;
    int tg = tid & 31, tn = tid >> 5;
    for (int idx = tid; idx < 2 * HH * HSTR; idx += 192) sH[idx] = 0.f;
    __syncthreads();

    int node0 = blockIdx.x * MT + tn * 8;
    int base = tn * 8;
    float c0[8], c1[8];
#pragma unroll
    for (int i = 0; i < 8; i++) { c0[i] = 0.f; c1[i] = 0.f; }

    int p = 0;
#pragma unroll 1
    for (int t = 0; t < DD; t++) {
        u64 acc[8][4];   // [gate j][node-pair m]
#pragma unroll
        for (int m = 0; m < 4; m++) {
            int na = node0 + 2 * m, nb = na + 1;
            int ia = (na < NN) ? g_nbrs[na * DD + t] : 0;
            int ib = (nb < NN) ? g_nbrs[nb * DD + t] : 0;
            const float* pa = g_proj + ia * GG + tg;
            const float* pb = g_proj + ib * GG + tg;
#pragma unroll
            for (int j = 0; j < 8; j++)
                acc[j][m] = pack2(__ldg(&pa[32 * j]), __ldg(&pb[32 * j]));
        }
        if (t) {
            const float* sHr = sH + p * (HH * HSTR);
#pragma unroll 2
            for (int k = 0; k < HH; k++) {
                const float* wk = g_wT + k * GG + tg;
                u64 bb[8];
#pragma unroll
                for (int j = 0; j < 8; j++) {
                    float b = __ldg(&wk[32 * j]);
                    bb[j] = pack2(b, b);
                }
#pragma unroll
                for (int m = 0; m < 4; m++) {
                    u64 a2 = *(const u64*)(sHr + k * HSTR + base + 2 * m);  // uniform bcast
#pragma unroll
                    for (int j = 0; j < 8; j++) acc[j][m] = fma2(a2, bb[j], acc[j][m]);
                }
            }
        }
        float* sHw = sH + (p ^ 1) * (HH * HSTR);
        bool last = (t == DD - 1);
#pragma unroll
        for (int m = 0; m < 4; m++) {
            float ga[8], gb[8];
#pragma unroll
            for (int j = 0; j < 8; j++) unpack2(acc[j][m], ga[j], gb[j]);
            // node a = 2m
            int ia = 2 * m;
            float iv0 = sigmx(ga[0]), iv1 = sigmx(ga[1]);
            float fv0 = sigmx(ga[2]), fv1 = sigmx(ga[3]);
            float gv0 = tanhx(ga[4]), gv1 = tanhx(ga[5]);
            float ov0 = sigmx(ga[6]), ov1 = sigmx(ga[7]);
            c0[ia] = fv0 * c0[ia] + iv0 * gv0;
            c1[ia] = fv1 * c1[ia] + iv1 * gv1;
            float h0a = ov0 * tanhx(c0[ia]);
            float h1a = ov1 * tanhx(c1[ia]);
            // node b = 2m+1
            int ib = 2 * m + 1;
            iv0 = sigmx(gb[0]); iv1 = sigmx(gb[1]);
            fv0 = sigmx(gb[2]); fv1 = sigmx(gb[3]);
            gv0 = tanhx(gb[4]); gv1 = tanhx(gb[5]);
            ov0 = sigmx(gb[6]); ov1 = sigmx(gb[7]);
            c0[ib] = fv0 * c0[ib] + iv0 * gv0;
            c1[ib] = fv1 * c1[ib] + iv1 * gv1;
            float h0b = ov0 * tanhx(c0[ib]);
            float h1b = ov1 * tanhx(c1[ib]);
            if (!last) {
                *(float2*)(sHw + tg * HSTR + base + 2 * m)        = make_float2(h0a, h0b);
                *(float2*)(sHw + (tg + 32) * HSTR + base + 2 * m) = make_float2(h1a, h1b);
            } else {
                int na = node0 + 2 * m, nb = na + 1;
                if (na < NN) {
                    g_agg[na * HH + tg]      = h0a;
                    g_agg[na * HH + tg + 32] = h1a;
                }
                if (nb < NN) {
                    g_agg[nb * HH + tg]      = h0b;
                    g_agg[nb * HH + tg + 32] = h1b;
                }
            }
        }
        __syncwarp();
        p ^= 1;
    }
}

// ---------------- h_next = relu([x, agg] @ Wl^T + bl)  (32 nodes/block) ---
__global__ void combine_kernel(const float* __restrict__ x, int in_d,
                               const float* __restrict__ Wl,
                               const float* __restrict__ bl,
                               float* __restrict__ out) {
    extern __shared__ float smf[];
    int C = in_d + HH;
    float* sW = smf;           // [C][64] transposed
    float* sB = sW + C * HH;   // [64]
    float* sX = sB + HH;       // [32][C]
    int tid = threadIdx.x;
    for (int idx = tid; idx < C * HH; idx += 256) {
        int o = idx / C, k = idx - o * C;
        sW[k * HH + o] = Wl[idx];
    }
    if (tid < HH) sB[tid] = bl[tid];
    int node0 = blockIdx.x * 32;
    for (int idx = tid; idx < 32 * C; idx += 256) {
        int i = idx / C, k = idx - i * C;
        sX[idx] = (k < in_d) ? x[(node0 + i) * in_d + k]
                             : g_agg[(node0 + i) * HH + (k - in_d)];
    }
    __syncthreads();
    int w = tid >> 5, tg = tid & 31;
    u64 acc[4];
#pragma unroll
    for (int i = 0; i < 4; i++) acc[i] = *(const u64*)(sB + 2 * tg);
    for (int k = 0; k < C; k++) {
        u64 wp = *(const u64*)(sW + k * HH + 2 * tg);
#pragma unroll
        for (int i = 0; i < 4; i++) {
            float xv = sX[(w * 4 + i) * C + k];
            acc[i] = fma2(pack2(xv, xv), wp, acc[i]);
        }
    }
#pragma unroll
    for (int i = 0; i < 4; i++) {
        float a0, a1;
        unpack2(acc[i], a0, a1);
        int node = node0 + w * 4 + i;
        *(float2*)(out + node * HH + 2 * tg) = make_float2(fmaxf(a0, 0.f), fmaxf(a1, 0.f));
    }
}

// ---------------- out = h @ W_out^T + b_out -------------------------------
__global__ void out_kernel(const float* __restrict__ h,
                           const float* __restrict__ W_out,
                           const float* __restrict__ b_out,
                           float* __restrict__ out) {
    int tid = threadIdx.x;
    int node = blockIdx.x * 8 + (tid >> 5);
    int tg = tid & 31;
    float a = h[node * HH + tg] * W_out[tg] + h[node * HH + tg + 32] * W_out[tg + 32];
#pragma unroll
    for (int s = 16; s > 0; s >>= 1) a += __shfl_down_sync(0xffffffffu, a, s);
    if (tg == 0) out[node] = a + b_out[0];
}

// ---------------- launcher ------------------------------------------------
extern "C" void kernel_launch(void* const* d_in, const int* in_sizes, int n_in,
                              void* d_out, int out_size) {
    const float* node_features = (const float*)d_in[0];
    const int*   nbr           = (const int*)d_in[1];
    const float *W_ih[3], *W_hh[3], *b_ih[3], *b_hh[3], *Wl[3], *bl[3];
    for (int l = 0; l < 3; l++) {
        W_ih[l] = (const float*)d_in[2 + 6 * l + 0];
        W_hh[l] = (const float*)d_in[2 + 6 * l + 1];
        b_ih[l] = (const float*)d_in[2 + 6 * l + 2];
        b_hh[l] = (const float*)d_in[2 + 6 * l + 3];
        Wl[l]   = (const float*)d_in[2 + 6 * l + 4];
        bl[l]   = (const float*)d_in[2 + 6 * l + 5];
    }
    const float* W_out = (const float*)d_in[20];
    const float* b_out = (const float*)d_in[21];
    float* out = (float*)d_out;

    float *bufA, *bufB;
    cudaGetSymbolAddress((void**)&bufA, g_bufA);
    cudaGetSymbolAddress((void**)&bufB, g_bufB);

    cudaFuncSetAttribute(proj_kernel, cudaFuncAttributeMaxDynamicSharedMemorySize, 80000);
    cudaFuncSetAttribute(combine_kernel, cudaFuncAttributeMaxDynamicSharedMemorySize, 56000);

    sort_kernel<<<(NN + 255) / 256, 256>>>(nbr);

    const float* x = node_features;
    float* nxt = bufA;
    int grid_lstm = (NN + MT - 1) / MT;   // 417
    for (int l = 0; l < 3; l++) {
        int in_d = (l == 0) ? 3 : 64;
        size_t proj_sm = (size_t)(in_d * GG + GG + 32 * in_d) * 4;
        transw_kernel<<<HH, GG>>>(W_hh[l]);
        proj_kernel<<<NN / 32, 256, proj_sm>>>(x, in_d, W_ih[l], b_ih[l], b_hh[l]);
        lstm_kernel<<<grid_lstm, 192>>>();
        int C = in_d + HH;
        size_t comb_sm = (size_t)(C * HH + HH + 32 * C) * 4;
        combine_kernel<<<NN / 32, 256, comb_sm>>>(x, in_d, Wl[l], bl[l], nxt);
        x = nxt;
        nxt = (nxt == bufA) ? bufB : bufA;
    }
    out_kernel<<<NN / 8, 256>>>(x, W_out, b_out, out);
}